// round 1
// baseline (speedup 1.0000x reference)
#include <cuda_runtime.h>
#include <cuda_bf16.h>
#include <cstdint>

// Problem constants
#define BATCH   4
#define SEQL    8192
#define DIM     1024
#define HEADS   8
#define CHUNK   32
#define NCHUNK  (SEQL / CHUNK)          // 256
#define NBLK    (BATCH * NCHUNK)        // 1024
#define THREADS 256                     // each thread owns 4 channels (float4)
#define LN_EPS  1e-5f

// Scratch: per-chunk end states (local EMA with zero carry-in) + flags + ticket
__device__ float g_yend[(size_t)NBLK * DIM];
__device__ int   g_sync[NBLK + 1];      // [0..NBLK): publish flags, [NBLK]: ticket counter

__device__ __forceinline__ int ld_acquire(const int* p) {
    int v;
    asm volatile("ld.global.acquire.gpu.b32 %0, [%1];" : "=r"(v) : "l"(p));
    return v;
}
__device__ __forceinline__ void st_release(int* p, int v) {
    asm volatile("st.global.release.gpu.b32 [%0], %1;" :: "l"(p), "r"(v));
}

extern "C" __global__ void __launch_bounds__(THREADS, 1)
mhesa_kernel(const float* __restrict__ x,
             const float* __restrict__ gamma,
             const float* __restrict__ beta,
             const float* __restrict__ alphas,
             const float* __restrict__ paramD,
             float* __restrict__ out)
{
    extern __shared__ float xbuf[];            // [CHUNK][DIM] = 128 KB
    __shared__ float s_mean[CHUNK];
    __shared__ float s_rstd[CHUNK];
    __shared__ int   s_ticket;

    const int tid  = threadIdx.x;
    const int lane = tid & 31;
    const int w    = tid >> 5;

    // Ticket assigns (b, chunk) in scheduling order -> lookback is deadlock-free.
    if (tid == 0) s_ticket = atomicAdd(&g_sync[NBLK], 1);
    __syncthreads();
    const int t = s_ticket;
    const int b = t & (BATCH - 1);
    const int c = t >> 2;                      // chunk index 0..NCHUNK-1

    const size_t base = ((size_t)b * SEQL + (size_t)c * CHUNK) * DIM;
    const float4* __restrict__ xc = (const float4*)(x + base);

    // ---------------- Phase A: stage x -> smem, LayerNorm stats per row ------
    {
        float4* sb = (float4*)xbuf;
        #pragma unroll
        for (int j = 0; j < 4; j++) {
            const int r = w * 4 + j;           // row within chunk
            float s = 0.f, ss = 0.f;
            #pragma unroll
            for (int i = 0; i < 8; i++) {
                float4 v = xc[(size_t)r * (DIM / 4) + i * 32 + lane];
                sb[r * (DIM / 4) + i * 32 + lane] = v;
                s  += (v.x + v.y) + (v.z + v.w);
                ss += v.x * v.x + v.y * v.y + v.z * v.z + v.w * v.w;
            }
            #pragma unroll
            for (int o = 16; o; o >>= 1) {
                s  += __shfl_xor_sync(0xffffffffu, s,  o);
                ss += __shfl_xor_sync(0xffffffffu, ss, o);
            }
            if (lane == 0) {
                float m   = s * (1.f / DIM);
                float var = ss * (1.f / DIM) - m * m;
                s_mean[r] = m;
                s_rstd[r] = rsqrtf(var + LN_EPS);
            }
        }
    }
    __syncthreads();

    // ---------------- Phase B: local EMA over chunk (thread owns 4 channels) -
    const float4 gm = ((const float4*)gamma )[tid];
    const float4 bt = ((const float4*)beta  )[tid];
    const float4 pd = ((const float4*)paramD)[tid];
    const float  alp = alphas[tid >> 5];       // head = (4*tid)>>7 = tid>>5, warp-uniform
    const float  a   = 1.f / (1.f + expf(-alp));
    const float  dec = 1.f - a;

    float4* xb4 = (float4*)xbuf;
    float4 y = make_float4(0.f, 0.f, 0.f, 0.f);

    #pragma unroll 8
    for (int l = 0; l < CHUNK; l++) {
        float4 v = xb4[l * (DIM / 4) + tid];
        const float m  = s_mean[l];
        const float rs = s_rstd[l];
        float4 u;
        u.x = (v.x - m) * rs * gm.x + bt.x;
        u.y = (v.y - m) * rs * gm.y + bt.y;
        u.z = (v.z - m) * rs * gm.z + bt.z;
        u.w = (v.w - m) * rs * gm.w + bt.w;
        y.x = fmaf(dec, y.x, a * u.x);
        y.y = fmaf(dec, y.y, a * u.y);
        y.z = fmaf(dec, y.z, a * u.z);
        y.w = fmaf(dec, y.w, a * u.w);
        float4 r;
        r.x = fmaf(u.x, pd.x, y.x);
        r.y = fmaf(u.y, pd.y, y.y);
        r.z = fmaf(u.z, pd.z, y.z);
        r.w = fmaf(u.w, pd.w, y.w);
        xb4[l * (DIM / 4) + tid] = r;          // stash y_local + u*paramD
    }

    // ---------------- Publish local end-state --------------------------------
    {
        float4* ye = (float4*)g_yend + (size_t)(b * NCHUNK + c) * (DIM / 4);
        ye[tid] = y;
    }
    __threadfence();
    __syncthreads();
    if (tid == 0) st_release(&g_sync[b * NCHUNK + c], 1);

    // ---------------- Decoupled lookback: accumulate carry-in ----------------
    float4 carry = make_float4(0.f, 0.f, 0.f, 0.f);
    if (c > 0) {
        float dch = dec;                       // dec^32 via 5 squarings
        #pragma unroll
        for (int i = 0; i < 5; i++) dch *= dch;
        float f = 1.f;
        int p = c - 1;
        const float4* yeb = (const float4*)g_yend + (size_t)b * NCHUNK * (DIM / 4);
        do {
            if (lane == 0) {
                while (ld_acquire(&g_sync[b * NCHUNK + p]) == 0) {}
            }
            __syncwarp();
            float4 v = __ldcg(yeb + (size_t)p * (DIM / 4) + tid);
            carry.x = fmaf(f, v.x, carry.x);
            carry.y = fmaf(f, v.y, carry.y);
            carry.z = fmaf(f, v.z, carry.z);
            carry.w = fmaf(f, v.w, carry.w);
            f *= dch;
            p--;
        } while (p >= 0 && f > 1e-10f);        // warp-uniform (head per warp)
    }

    // ---------------- Fixup + store ------------------------------------------
    float4* __restrict__ oc = (float4*)(out + base);
    float pw = dec;                            // dec^(l_local+1)
    #pragma unroll 8
    for (int l = 0; l < CHUNK; l++) {
        float4 v = xb4[l * (DIM / 4) + tid];
        v.x = fmaf(carry.x, pw, v.x);
        v.y = fmaf(carry.y, pw, v.y);
        v.z = fmaf(carry.z, pw, v.z);
        v.w = fmaf(carry.w, pw, v.w);
        oc[l * (DIM / 4) + tid] = v;
        pw *= dec;
    }
}

extern "C" void kernel_launch(void* const* d_in, const int* in_sizes, int n_in,
                              void* d_out, int out_size)
{
    const float* x      = (const float*)d_in[0];
    const float* gamma  = (const float*)d_in[1];
    const float* beta   = (const float*)d_in[2];
    const float* alphas = (const float*)d_in[3];
    const float* paramD = (const float*)d_in[4];
    float* out = (float*)d_out;

    // Reset flags + ticket (capture-legal stream memset).
    void* sym = nullptr;
    cudaGetSymbolAddress(&sym, g_sync);
    cudaMemsetAsync(sym, 0, sizeof(int) * (NBLK + 1), 0);

    static bool attr_done = false;
    const int smem_bytes = CHUNK * DIM * sizeof(float);   // 131072
    if (!attr_done) {
        cudaFuncSetAttribute(mhesa_kernel,
                             cudaFuncAttributeMaxDynamicSharedMemorySize, smem_bytes);
        attr_done = true;
    }

    mhesa_kernel<<<NBLK, THREADS, smem_bytes>>>(x, gamma, beta, alphas, paramD, out);
}

// round 2
// speedup vs baseline: 1.0809x; 1.0809x over previous
#include <cuda_runtime.h>
#include <cuda_bf16.h>
#include <cstdint>

// Problem constants
#define BATCH   4
#define SEQL    8192
#define DIM     1024
#define HEADS   8
#define CHUNK   16
#define NCHUNK  (SEQL / CHUNK)          // 512
#define NBLK    (BATCH * NCHUNK)        // 2048
#define THREADS 256                     // each thread owns 4 channels (float4)
#define LN_EPS  1e-5f

// Scratch: per-chunk end states (local EMA with zero carry-in) + flags + ticket
__device__ float g_yend[(size_t)NBLK * DIM];
__device__ int   g_sync[NBLK + 1];      // [0..NBLK): publish flags, [NBLK]: ticket counter

__device__ __forceinline__ int ld_acquire(const int* p) {
    int v;
    asm volatile("ld.global.acquire.gpu.b32 %0, [%1];" : "=r"(v) : "l"(p));
    return v;
}
__device__ __forceinline__ void st_release(int* p, int v) {
    asm volatile("st.global.release.gpu.b32 [%0], %1;" :: "l"(p), "r"(v));
}

extern "C" __global__ void __launch_bounds__(THREADS, 3)
mhesa_kernel(const float* __restrict__ x,
             const float* __restrict__ gamma,
             const float* __restrict__ beta,
             const float* __restrict__ alphas,
             const float* __restrict__ paramD,
             float* __restrict__ out)
{
    extern __shared__ float xbuf[];            // [CHUNK][DIM] = 64 KB
    __shared__ float s_mean[CHUNK];
    __shared__ float s_rstd[CHUNK];
    __shared__ int   s_ticket;

    const int tid  = threadIdx.x;
    const int lane = tid & 31;
    const int w    = tid >> 5;

    // Ticket assigns (b, chunk) in scheduling order -> lookback is deadlock-free.
    // Consecutive tickets hit different batches, spreading each batch's serial chain.
    if (tid == 0) s_ticket = atomicAdd(&g_sync[NBLK], 1);
    __syncthreads();
    const int t = s_ticket;
    const int b = t & (BATCH - 1);
    const int c = t >> 2;                      // chunk index 0..NCHUNK-1

    const size_t base = ((size_t)b * SEQL + (size_t)c * CHUNK) * DIM;
    const float4* __restrict__ xc = (const float4*)(x + base);

    // ---------------- Phase A: stage x -> smem, LayerNorm stats per row ------
    {
        float4* sb = (float4*)xbuf;
        #pragma unroll
        for (int j = 0; j < CHUNK / 8; j++) {  // 2 rows per warp
            const int r = w * (CHUNK / 8) + j;
            float s = 0.f, ss = 0.f;
            #pragma unroll
            for (int i = 0; i < 8; i++) {
                float4 v = xc[(size_t)r * (DIM / 4) + i * 32 + lane];
                sb[r * (DIM / 4) + i * 32 + lane] = v;
                s  += (v.x + v.y) + (v.z + v.w);
                ss += v.x * v.x + v.y * v.y + v.z * v.z + v.w * v.w;
            }
            #pragma unroll
            for (int o = 16; o; o >>= 1) {
                s  += __shfl_xor_sync(0xffffffffu, s,  o);
                ss += __shfl_xor_sync(0xffffffffu, ss, o);
            }
            if (lane == 0) {
                float m   = s * (1.f / DIM);
                float var = ss * (1.f / DIM) - m * m;
                s_mean[r] = m;
                s_rstd[r] = rsqrtf(var + LN_EPS);
            }
        }
    }
    __syncthreads();

    // ---------------- Phase B: local EMA over chunk (thread owns 4 channels) -
    const float4 gm = ((const float4*)gamma )[tid];
    const float4 bt = ((const float4*)beta  )[tid];
    const float4 pd = ((const float4*)paramD)[tid];
    const float  alp = alphas[tid >> 5];       // head = (4*tid)>>7 = tid>>5, warp-uniform
    const float  a   = 1.f / (1.f + expf(-alp));
    const float  dec = 1.f - a;

    float4* xb4 = (float4*)xbuf;
    float4 y = make_float4(0.f, 0.f, 0.f, 0.f);

    #pragma unroll 4
    for (int l = 0; l < CHUNK; l++) {
        float4 v = xb4[l * (DIM / 4) + tid];
        const float m  = s_mean[l];
        const float rs = s_rstd[l];
        float4 u;
        u.x = (v.x - m) * rs * gm.x + bt.x;
        u.y = (v.y - m) * rs * gm.y + bt.y;
        u.z = (v.z - m) * rs * gm.z + bt.z;
        u.w = (v.w - m) * rs * gm.w + bt.w;
        y.x = fmaf(dec, y.x, a * u.x);
        y.y = fmaf(dec, y.y, a * u.y);
        y.z = fmaf(dec, y.z, a * u.z);
        y.w = fmaf(dec, y.w, a * u.w);
        float4 r;
        r.x = fmaf(u.x, pd.x, y.x);
        r.y = fmaf(u.y, pd.y, y.y);
        r.z = fmaf(u.z, pd.z, y.z);
        r.w = fmaf(u.w, pd.w, y.w);
        xb4[l * (DIM / 4) + tid] = r;          // stash y_local + u*paramD
    }

    // ---------------- Publish local end-state --------------------------------
    {
        float4* ye = (float4*)g_yend + (size_t)(b * NCHUNK + c) * (DIM / 4);
        ye[tid] = y;
    }
    __threadfence();
    __syncthreads();
    if (tid == 0) st_release(&g_sync[b * NCHUNK + c], 1);

    // ---------------- Decoupled lookback: accumulate carry-in ----------------
    float4 carry = make_float4(0.f, 0.f, 0.f, 0.f);
    if (c > 0) {
        float dch = dec;                       // dec^CHUNK via 4 squarings
        #pragma unroll
        for (int i = 0; i < 4; i++) dch *= dch;
        float f = 1.f;
        int p = c - 1;
        const float4* yeb = (const float4*)g_yend + (size_t)b * NCHUNK * (DIM / 4);
        do {
            if (lane == 0) {
                while (ld_acquire(&g_sync[b * NCHUNK + p]) == 0) {}
            }
            __syncwarp();
            float4 v = __ldcg(yeb + (size_t)p * (DIM / 4) + tid);
            carry.x = fmaf(f, v.x, carry.x);
            carry.y = fmaf(f, v.y, carry.y);
            carry.z = fmaf(f, v.z, carry.z);
            carry.w = fmaf(f, v.w, carry.w);
            f *= dch;
            p--;
        } while (p >= 0 && f > 1e-7f);         // warp-uniform (head per warp)
    }

    // ---------------- Fixup + store ------------------------------------------
    float4* __restrict__ oc = (float4*)(out + base);
    float pw = dec;                            // dec^(l_local+1)
    #pragma unroll 4
    for (int l = 0; l < CHUNK; l++) {
        float4 v = xb4[l * (DIM / 4) + tid];
        v.x = fmaf(carry.x, pw, v.x);
        v.y = fmaf(carry.y, pw, v.y);
        v.z = fmaf(carry.z, pw, v.z);
        v.w = fmaf(carry.w, pw, v.w);
        oc[l * (DIM / 4) + tid] = v;
        pw *= dec;
    }
}

extern "C" void kernel_launch(void* const* d_in, const int* in_sizes, int n_in,
                              void* d_out, int out_size)
{
    const float* x      = (const float*)d_in[0];
    const float* gamma  = (const float*)d_in[1];
    const float* beta   = (const float*)d_in[2];
    const float* alphas = (const float*)d_in[3];
    const float* paramD = (const float*)d_in[4];
    float* out = (float*)d_out;

    // Reset flags + ticket (capture-legal stream memset).
    void* sym = nullptr;
    cudaGetSymbolAddress(&sym, g_sync);
    cudaMemsetAsync(sym, 0, sizeof(int) * (NBLK + 1), 0);

    static bool attr_done = false;
    const int smem_bytes = CHUNK * DIM * sizeof(float);   // 65536
    if (!attr_done) {
        cudaFuncSetAttribute(mhesa_kernel,
                             cudaFuncAttributeMaxDynamicSharedMemorySize, smem_bytes);
        attr_done = true;
    }

    mhesa_kernel<<<NBLK, THREADS, smem_bytes>>>(x, gamma, beta, alphas, paramD, out);
}

// round 3
// speedup vs baseline: 1.1668x; 1.0795x over previous
#include <cuda_runtime.h>
#include <cuda_bf16.h>
#include <cstdint>

// Problem constants
#define BATCH   4
#define SEQL    8192
#define DIM     1024
#define HEADS   8
#define SPAN    32                      // rows per main-kernel block
#define NSPAN   (SEQL / SPAN)           // 256
#define NBLK2   (BATCH * NSPAN)         // 1024
#define THREADS 256
#define LN_EPS  1e-5f
#define NROWS   (BATCH * SEQL)          // 32768

// Scratch
__device__ float2 g_stat[NROWS];                     // (mean, rstd) per row
__device__ float  g_yend[(size_t)NBLK2 * DIM];       // per-span local end state
__device__ int    g_sync[NBLK2 + 1];                 // publish flags + ticket

__device__ __forceinline__ int ld_acquire(const int* p) {
    int v;
    asm volatile("ld.global.acquire.gpu.b32 %0, [%1];" : "=r"(v) : "l"(p));
    return v;
}
__device__ __forceinline__ void st_release(int* p, int v) {
    asm volatile("st.global.release.gpu.b32 [%0], %1;" :: "l"(p), "r"(v));
}

// ---------------- Kernel 1: LayerNorm row statistics (pure streaming) --------
extern "C" __global__ void __launch_bounds__(256)
stats_kernel(const float* __restrict__ x)
{
    const int lane = threadIdx.x & 31;
    const int w    = threadIdx.x >> 5;
    const int row  = blockIdx.x * 8 + w;            // 8 rows per block
    const float4* __restrict__ xr = (const float4*)(x + (size_t)row * DIM);

    float s = 0.f, ss = 0.f;
    #pragma unroll
    for (int i = 0; i < 8; i++) {
        float4 v = xr[i * 32 + lane];
        s  += (v.x + v.y) + (v.z + v.w);
        ss += v.x * v.x + v.y * v.y + v.z * v.z + v.w * v.w;
    }
    #pragma unroll
    for (int o = 16; o; o >>= 1) {
        s  += __shfl_xor_sync(0xffffffffu, s,  o);
        ss += __shfl_xor_sync(0xffffffffu, ss, o);
    }
    if (lane == 0) {
        float m   = s * (1.f / DIM);
        float var = ss * (1.f / DIM) - m * m;
        g_stat[row] = make_float2(m, rsqrtf(var + LN_EPS));
    }
}

// ---------------- Kernel 2: streaming LN + EMA scan + lookback ---------------
extern "C" __global__ void __launch_bounds__(THREADS, 4)
mhesa_main(const float* __restrict__ x,
           const float* __restrict__ gamma,
           const float* __restrict__ beta,
           const float* __restrict__ alphas,
           const float* __restrict__ paramD,
           float* __restrict__ out)
{
    __shared__ float2 s_stat[SPAN];
    __shared__ int    s_ticket;

    const int tid  = threadIdx.x;
    const int lane = tid & 31;

    // Ticket: scheduling-order assignment -> lookback predecessors already running.
    if (tid == 0) s_ticket = atomicAdd(&g_sync[NBLK2], 1);
    __syncthreads();
    const int t = s_ticket;
    const int b = t & (BATCH - 1);
    const int c = t >> 2;                            // span index 0..NSPAN-1

    if (tid < SPAN)
        s_stat[tid] = g_stat[b * SEQL + c * SPAN + tid];
    __syncthreads();

    const float4 gm = ((const float4*)gamma )[tid];
    const float4 bt = ((const float4*)beta  )[tid];
    const float4 pd = ((const float4*)paramD)[tid];
    const float  alp = alphas[tid >> 5];             // head = tid>>5, warp-uniform
    const float  a   = 1.f / (1.f + expf(-alp));
    const float  dec = 1.f - a;

    const size_t base = ((size_t)b * SEQL + (size_t)c * SPAN) * DIM;
    const float4* __restrict__ xc = (const float4*)(x + base);
    float4* __restrict__ oc = (float4*)(out + base);

    // -------- Streaming pass: load x, LN, EMA (zero carry-in), store ---------
    float4 y = make_float4(0.f, 0.f, 0.f, 0.f);
    #pragma unroll 4
    for (int l = 0; l < SPAN; l++) {
        float4 v = xc[l * (DIM / 4) + tid];
        const float m  = s_stat[l].x;
        const float rs = s_stat[l].y;
        float4 u;
        u.x = (v.x - m) * rs * gm.x + bt.x;
        u.y = (v.y - m) * rs * gm.y + bt.y;
        u.z = (v.z - m) * rs * gm.z + bt.z;
        u.w = (v.w - m) * rs * gm.w + bt.w;
        y.x = fmaf(dec, y.x, a * u.x);
        y.y = fmaf(dec, y.y, a * u.y);
        y.z = fmaf(dec, y.z, a * u.z);
        y.w = fmaf(dec, y.w, a * u.w);
        float4 r;
        r.x = fmaf(u.x, pd.x, y.x);
        r.y = fmaf(u.y, pd.y, y.y);
        r.z = fmaf(u.z, pd.z, y.z);
        r.w = fmaf(u.w, pd.w, y.w);
        oc[l * (DIM / 4) + tid] = r;                 // local result (pre-fixup)
    }

    // -------- Publish local end-state ----------------------------------------
    {
        float4* ye = (float4*)g_yend + (size_t)(b * NSPAN + c) * (DIM / 4);
        ye[tid] = y;
    }
    __threadfence();
    __syncthreads();
    if (tid == 0) st_release(&g_sync[b * NSPAN + c], 1);

    // -------- Decoupled lookback: accumulate carry-in ------------------------
    float4 carry = make_float4(0.f, 0.f, 0.f, 0.f);
    if (c > 0) {
        float dch = dec;                             // dec^SPAN via 5 squarings
        #pragma unroll
        for (int i = 0; i < 5; i++) dch *= dch;
        float f = 1.f;
        int p = c - 1;
        const float4* yeb = (const float4*)g_yend + (size_t)b * NSPAN * (DIM / 4);
        do {
            if (lane == 0) {
                while (ld_acquire(&g_sync[b * NSPAN + p]) == 0) {}
            }
            __syncwarp();
            float4 v = __ldcg(yeb + (size_t)p * (DIM / 4) + tid);
            carry.x = fmaf(f, v.x, carry.x);
            carry.y = fmaf(f, v.y, carry.y);
            carry.z = fmaf(f, v.z, carry.z);
            carry.w = fmaf(f, v.w, carry.w);
            f *= dch;
            p--;
        } while (p >= 0 && f > 1e-6f);               // warp-uniform loop

        // -------- Fixup: add carry * dec^(l+1), truncated by decay ------------
        float cm = fmaxf(fmaxf(fabsf(carry.x), fabsf(carry.y)),
                         fmaxf(fabsf(carry.z), fabsf(carry.w)));
        #pragma unroll
        for (int o = 16; o; o >>= 1)
            cm = fmaxf(cm, __shfl_xor_sync(0xffffffffu, cm, o));

        float pw = dec;
        for (int l = 0; l < SPAN && pw * cm > 1e-6f; l++) {
            float4 v = oc[l * (DIM / 4) + tid];      // same-thread RAW: ordered
            v.x = fmaf(carry.x, pw, v.x);
            v.y = fmaf(carry.y, pw, v.y);
            v.z = fmaf(carry.z, pw, v.z);
            v.w = fmaf(carry.w, pw, v.w);
            oc[l * (DIM / 4) + tid] = v;
            pw *= dec;
        }
    }
}

extern "C" void kernel_launch(void* const* d_in, const int* in_sizes, int n_in,
                              void* d_out, int out_size)
{
    const float* x      = (const float*)d_in[0];
    const float* gamma  = (const float*)d_in[1];
    const float* beta   = (const float*)d_in[2];
    const float* alphas = (const float*)d_in[3];
    const float* paramD = (const float*)d_in[4];
    float* out = (float*)d_out;

    // Reset flags + ticket (capture-legal stream memset).
    void* sym = nullptr;
    cudaGetSymbolAddress(&sym, g_sync);
    cudaMemsetAsync(sym, 0, sizeof(int) * (NBLK2 + 1), 0);

    stats_kernel<<<NROWS / 8, 256>>>(x);
    mhesa_main<<<NBLK2, THREADS>>>(x, gamma, beta, alphas, paramD, out);
}